// round 1
// baseline (speedup 1.0000x reference)
#include <cuda_runtime.h>

// ============================================================================
// HybridLoss: B=2, T=4, N=4096
// total = 0.5*mean(chamfer) + 0.5*mean(temperature-softmax hausdorff)
//
// Structure:
//  k0 detect_mask_kernel : determine on-device dtype of the bool masks
//  k1 dist_kernel        : grid (16,8,2) -> min_p / min_t per (bt, row)
//  k2 reduce_kernel      : grid (8)      -> per-(b,t) chamfer + soft-hausdorff
//  k3 final_kernel       : combine 8 values -> scalar
// ============================================================================

#define ALPHA_C  0.5f
#define INV_TEMP 10.0f          // 1 / 0.1
#define BIGF     10000000000.0f
#define THRESHF  1000000000.0f

constexpr int B_  = 2;
constexpr int T_  = 4;
constexpr int N_  = 4096;
constexpr int BT_ = 8;

constexpr int THREADS = 128;    // dist kernel block size
constexpr int RPT     = 2;      // rows per thread
constexpr int ROWS_PER_BLOCK = THREADS * RPT;   // 256
constexpr int TILES   = N_ / ROWS_PER_BLOCK;    // 16
constexpr int CCHUNK  = 512;    // columns staged in shared per iteration

// Scratch (no cudaMalloc allowed)
__device__ float g_min[2][BT_][N_];   // [pass][bt][n]: pass0=min_p, pass1=min_t
__device__ float g_cd[BT_];
__device__ float g_hd[BT_];
__device__ int   g_mask_mode;         // 0=uint8/bool, 1=int32, 2=float32

// ---------------------------------------------------------------------------
// Mask dtype detection. padding_mask is ~95% ones.
//   uint8 bool : bytes at i%4==1 are ~95% nonzero
//   int32 0/1  : bytes at i%4!=0 all zero
//   float 0/1.0: byte at i%4==1 zero, byte at i%4==2 ~95% nonzero (0x80)
// ---------------------------------------------------------------------------
__global__ void detect_mask_kernel(const unsigned char* __restrict__ pad) {
    __shared__ int c1, c2;
    if (threadIdx.x == 0) { c1 = 0; c2 = 0; }
    __syncthreads();
    int l1 = 0, l2 = 0;
    for (int i = threadIdx.x; i < 2048; i += blockDim.x) {
        if (pad[4 * i + 1]) l1++;
        if (pad[4 * i + 2]) l2++;
    }
    atomicAdd(&c1, l1);
    atomicAdd(&c2, l2);
    __syncthreads();
    if (threadIdx.x == 0)
        g_mask_mode = (c1 > 64) ? 0 : ((c2 > 64) ? 2 : 1);
}

__device__ __forceinline__ bool ldmask(const void* p, int i, int mode) {
    if (mode == 0) return ((const unsigned char*)p)[i] != 0;
    if (mode == 1) return ((const int*)p)[i] != 0;
    return ((const float*)p)[i] != 0.0f;
}

// ---------------------------------------------------------------------------
// Pairwise-min kernel.
//   pass 0: rows = pred,   cols = target  -> min_p
//   pass 1: rows = target, cols = pred    -> min_t
// Column bias s_m = |c_m|^2 + (mask_m ? 0 : BIG). Row norm |r_n|^2 deferred
// out of the min. Final clamp fmax(.,0) == reference's per-element clamp.
// ---------------------------------------------------------------------------
__global__ void __launch_bounds__(THREADS) dist_kernel(
    const float* __restrict__ pred, const float* __restrict__ tgt,
    const void* __restrict__ isctl, const void* __restrict__ pad,
    const void* __restrict__ vis)
{
    __shared__ float4 sc[CCHUNK];

    const int tile = blockIdx.x;
    const int bt   = blockIdx.y;
    const int pass = blockIdx.z;
    const int b    = bt >> 2;          // T_ = 4
    const int mode = g_mask_mode;

    const float* __restrict__ rowp = (pass == 0) ? pred : tgt;
    const float* __restrict__ colp = (pass == 0) ? tgt  : pred;

    float px[RPT], py[RPT], pz[RPT], pn[RPT], rmin[RPT];
    const int rbase = tile * ROWS_PER_BLOCK + threadIdx.x;
#pragma unroll
    for (int r = 0; r < RPT; r++) {
        const int row = rbase + r * THREADS;
        const float* rp = rowp + ((size_t)bt * N_ + row) * 3;
        px[r] = rp[0]; py[r] = rp[1]; pz[r] = rp[2];
        pn[r] = fmaf(px[r], px[r], fmaf(py[r], py[r], pz[r] * pz[r]));
        rmin[r] = 3.0e38f;
    }

    for (int base = 0; base < N_; base += CCHUNK) {
        __syncthreads();   // previous chunk's compute done before restaging
        for (int j = threadIdx.x; j < CCHUNK; j += THREADS) {
            const int m = base + j;
            const float* cp = colp + ((size_t)bt * N_ + m) * 3;
            const float x = cp[0], y = cp[1], z = cp[2];
            const bool msk = !ldmask(isctl, b * N_ + m, mode)
                           &&  ldmask(pad,   b * N_ + m, mode)
                           &&  ldmask(vis,  bt * N_ + m, mode);
            const float s = fmaf(x, x, fmaf(y, y, z * z)) + (msk ? 0.0f : BIGF);
            sc[j] = make_float4(x, y, z, s);
        }
        __syncthreads();

#pragma unroll 4
        for (int j = 0; j < CCHUNK; j++) {
            const float4 c = sc[j];
#pragma unroll
            for (int r = 0; r < RPT; r++) {
                const float dot = fmaf(px[r], c.x, fmaf(py[r], c.y, pz[r] * c.z));
                const float v   = fmaf(dot, -2.0f, c.w);
                rmin[r] = fminf(rmin[r], v);
            }
        }
    }

#pragma unroll
    for (int r = 0; r < RPT; r++) {
        const int row = rbase + r * THREADS;
        g_min[pass][bt][row] = fmaxf(rmin[r] + pn[r], 0.0f);
    }
}

// ---------------------------------------------------------------------------
// Per-(b,t) reduction: chamfer terms + temperature soft-max hausdorff.
// ---------------------------------------------------------------------------
__device__ __forceinline__ float blockSum(float v, float* s) {
    const int tid = threadIdx.x;
    s[tid] = v; __syncthreads();
    for (int off = 128; off > 0; off >>= 1) {
        if (tid < off) s[tid] += s[tid + off];
        __syncthreads();
    }
    const float r = s[0]; __syncthreads();
    return r;
}
__device__ __forceinline__ float blockMax(float v, float* s) {
    const int tid = threadIdx.x;
    s[tid] = v; __syncthreads();
    for (int off = 128; off > 0; off >>= 1) {
        if (tid < off) s[tid] = fmaxf(s[tid], s[tid + off]);
        __syncthreads();
    }
    const float r = s[0]; __syncthreads();
    return r;
}

__global__ void __launch_bounds__(256) reduce_kernel(
    const void* __restrict__ isctl, const void* __restrict__ pad,
    const void* __restrict__ vis)
{
    __shared__ float sred[256];
    const int bt   = blockIdx.x;
    const int b    = bt >> 2;
    const int mode = g_mask_mode;
    const int tid  = threadIdx.x;
    constexpr int K = N_ / 256;   // 16

    float nv = 0.f, cdp = 0.f, cdt = 0.f;
    float mxp = -3.0e38f, mxt = -3.0e38f;
    float hp[K], ht[K];
    bool  mk[K];

#pragma unroll
    for (int k = 0; k < K; k++) {
        const int n = tid + k * 256;
        const bool msk = !ldmask(isctl, b * N_ + n, mode)
                       &&  ldmask(pad,   b * N_ + n, mode)
                       &&  ldmask(vis,  bt * N_ + n, mode);
        mk[k] = msk;
        const float mp = g_min[0][bt][n];
        const float mt = g_min[1][bt][n];
        if (msk) {
            nv  += 1.0f;
            cdp += (mp > THRESHF) ? 0.0f : mp;
            cdt += (mt > THRESHF) ? 0.0f : mt;
            hp[k] = fminf(mp, THRESHF);
            ht[k] = fminf(mt, THRESHF);
            mxp = fmaxf(mxp, hp[k]);
            mxt = fmaxf(mxt, ht[k]);
        } else { hp[k] = 0.f; ht[k] = 0.f; }
    }

    const float nvT  = blockSum(nv,  sred);
    const float cdpT = blockSum(cdp, sred);
    const float cdtT = blockSum(cdt, sred);
    const float Mp   = blockMax(mxp, sred);
    const float Mt   = blockMax(mxt, sred);
    const bool  anyv = (Mp > -1.0e30f);   // == any(mask)

    // Masked-out entries contribute exactly 0 in the reference (w underflows
    // to 0), so skipping them is exact.
    float sep = 0.f, shp = 0.f, set = 0.f, sht = 0.f;
#pragma unroll
    for (int k = 0; k < K; k++) {
        if (mk[k]) {
            const float ep = expf((hp[k] - Mp) * INV_TEMP);
            sep += ep; shp += hp[k] * ep;
            const float et = expf((ht[k] - Mt) * INV_TEMP);
            set += et; sht += ht[k] * et;
        }
    }
    const float sepT = blockSum(sep, sred);
    const float shpT = blockSum(shp, sred);
    const float setT = blockSum(set, sred);
    const float shtT = blockSum(sht, sred);

    if (tid == 0) {
        const float nvc = fmaxf(nvT, 1.0f);
        g_cd[bt] = cdpT / nvc + cdtT / nvc;
        const float rp = anyv ? (shpT / sepT) : 0.0f;
        const float rt = anyv ? (shtT / setT) : 0.0f;
        g_hd[bt] = fmaxf(rp, rt);
    }
}

__global__ void final_kernel(float* __restrict__ out) {
    if (threadIdx.x == 0) {
        float cd = 0.f, hd = 0.f;
        for (int i = 0; i < BT_; i++) { cd += g_cd[i]; hd += g_hd[i]; }
        out[0] = ALPHA_C * (cd / (float)BT_) + (1.0f - ALPHA_C) * (hd / (float)BT_);
    }
}

// ---------------------------------------------------------------------------
extern "C" void kernel_launch(void* const* d_in, const int* in_sizes, int n_in,
                              void* d_out, int out_size) {
    const float* pred = (const float*)d_in[0];
    const float* tgt  = (const float*)d_in[1];
    const void*  isc  = d_in[2];
    const void*  pad  = d_in[3];
    const void*  vis  = d_in[4];

    detect_mask_kernel<<<1, 256>>>((const unsigned char*)pad);
    dist_kernel<<<dim3(TILES, BT_, 2), THREADS>>>(pred, tgt, isc, pad, vis);
    reduce_kernel<<<BT_, 256>>>(isc, pad, vis);
    final_kernel<<<1, 32>>>((float*)d_out);
}

// round 2
// speedup vs baseline: 1.3612x; 1.3612x over previous
#include <cuda_runtime.h>

// ============================================================================
// HybridLoss: B=2, T=4, N=4096
// Single-pass dual-min: u(n,m) = (rn+rowBias) + (cn+colBias) - 2*dot
//   row-min(u) -> min_p (valid rows exact), col-min(u) -> min_t (valid cols
//   exact). Corrupted entries are discarded downstream by the mask.
// ============================================================================

#define ALPHA_C  0.5f
#define INV_TEMP 10.0f
#define BIGF     10000000000.0f
#define THRESHF  1000000000.0f

constexpr int N_  = 4096;
constexpr int BT_ = 8;

// dist kernel geometry
constexpr int TX = 16;              // thread cols
constexpr int TY = 8;               // thread rows
constexpr int RPT = 8;              // rows per thread
constexpr int CPT = 8;              // cols per thread per chunk
constexpr int ROWS_BLK = TY * RPT;  // 64 rows per block
constexpr int CCH      = TX * CPT;  // 128 cols per chunk
constexpr int ROWBLKS  = N_ / ROWS_BLK;  // 64
constexpr int NCHUNKS  = N_ / CCH;       // 32

// Scratch (static device arrays only — no allocation allowed)
__device__ float g_min[2][BT_][N_];           // [0]=min_p, [1]=min_t
__device__ float g_colpart[BT_][ROWBLKS][N_]; // col-min partials (8 MB)
__device__ float g_cd[BT_];
__device__ float g_hd[BT_];
__device__ int   g_mask_mode;                 // 0=u8/bool 1=int32 2=float32

// ---------------------------------------------------------------------------
__global__ void detect_mask_kernel(const unsigned char* __restrict__ pad) {
    __shared__ int c1, c2;
    if (threadIdx.x == 0) { c1 = 0; c2 = 0; }
    __syncthreads();
    int l1 = 0, l2 = 0;
    for (int i = threadIdx.x; i < 2048; i += blockDim.x) {
        if (pad[4 * i + 1]) l1++;
        if (pad[4 * i + 2]) l2++;
    }
    atomicAdd(&c1, l1);
    atomicAdd(&c2, l2);
    __syncthreads();
    if (threadIdx.x == 0)
        g_mask_mode = (c1 > 64) ? 0 : ((c2 > 64) ? 2 : 1);
}

__device__ __forceinline__ bool ldmask(const void* p, int i, int mode) {
    if (mode == 0) return ((const unsigned char*)p)[i] != 0;
    if (mode == 1) return ((const int*)p)[i] != 0;
    return ((const float*)p)[i] != 0.0f;
}

// ---------------------------------------------------------------------------
// Dual-min pairwise kernel. Block = 64 pred rows x full 4096 target cols.
// tid = tx*8 + ty  (ty = low 3 bits -> 8 consecutive lanes share cols)
// ---------------------------------------------------------------------------
__global__ void __launch_bounds__(128, 4) dist_kernel(
    const float* __restrict__ pred, const float* __restrict__ tgt,
    const void* __restrict__ isctl, const void* __restrict__ pad,
    const void* __restrict__ vis)
{
    __shared__ float4 sc[CCH];                 // staged cols: (-2x,-2y,-2z,cw)
    __shared__ float  sr[128 * RPT];           // row-min partials (end only)

    const int rowblk = blockIdx.x;
    const int bt     = blockIdx.y;
    const int b      = bt >> 2;
    const int mode   = g_mask_mode;
    const int tid    = threadIdx.x;
    const int tx     = tid >> 3;
    const int ty     = tid & 7;

    // Load this thread's 8 rows (pred), fold row bias into rw.
    float px[RPT], py[RPT], pz[RPT], rw[RPT], rmin[RPT];
    const int rbase = rowblk * ROWS_BLK + ty * RPT;
#pragma unroll
    for (int r = 0; r < RPT; r++) {
        const int row = rbase + r;
        const float* rp = pred + ((size_t)bt * N_ + row) * 3;
        px[r] = rp[0]; py[r] = rp[1]; pz[r] = rp[2];
        const bool msk = !ldmask(isctl, b * N_ + row, mode)
                       &&  ldmask(pad,   b * N_ + row, mode)
                       &&  ldmask(vis,  bt * N_ + row, mode);
        rw[r] = fmaf(px[r], px[r], fmaf(py[r], py[r], pz[r] * pz[r]))
              + (msk ? 0.0f : BIGF);
        rmin[r] = 3.0e38f;
    }

    for (int chunk = 0; chunk < NCHUNKS; chunk++) {
        __syncthreads();   // previous chunk's reads done before restage
        {
            const int m = chunk * CCH + tid;
            const float* cp = tgt + ((size_t)bt * N_ + m) * 3;
            const float x = cp[0], y = cp[1], z = cp[2];
            const bool msk = !ldmask(isctl, b * N_ + m, mode)
                           &&  ldmask(pad,   b * N_ + m, mode)
                           &&  ldmask(vis,  bt * N_ + m, mode);
            const float cw = fmaf(x, x, fmaf(y, y, z * z))
                           + (msk ? 0.0f : BIGF);
            sc[tid] = make_float4(-2.0f * x, -2.0f * y, -2.0f * z, cw);
        }
        __syncthreads();

        float cmin[CPT];
#pragma unroll
        for (int j = 0; j < CPT; j++) {
            const float4 c = sc[tx * CPT + j];
            float cm = 3.0e38f;
#pragma unroll
            for (int r = 0; r < RPT; r++) {
                // u = rn' + cn' - 2*dot  (4 fma-pipe ops)
                const float u = fmaf(px[r], c.x,
                                fmaf(py[r], c.y,
                                fmaf(pz[r], c.z, c.w + rw[r])));
                rmin[r] = fminf(rmin[r], u);
                cm      = fminf(cm, u);
            }
            cmin[j] = cm;
        }

        // col-min across the 8 ty-lanes (consecutive within warp)
#pragma unroll
        for (int j = 0; j < CPT; j++) {
            cmin[j] = fminf(cmin[j], __shfl_xor_sync(0xffffffffu, cmin[j], 4));
            cmin[j] = fminf(cmin[j], __shfl_xor_sync(0xffffffffu, cmin[j], 2));
            cmin[j] = fminf(cmin[j], __shfl_xor_sync(0xffffffffu, cmin[j], 1));
        }
        if (ty == 0) {
            float* dst = &g_colpart[bt][rowblk][chunk * CCH + tx * CPT];
#pragma unroll
            for (int j = 0; j < CPT; j++) dst[j] = cmin[j];
        }
    }

    // Row-min: reduce across the 16 tx groups via shared memory.
    __syncthreads();
#pragma unroll
    for (int r = 0; r < RPT; r++) sr[tid * RPT + r] = rmin[r];
    __syncthreads();
    if (tid < ROWS_BLK) {
        const int rty = tid >> 3, rr = tid & 7;
        float v = 3.0e38f;
#pragma unroll
        for (int t = 0; t < TX; t++)
            v = fminf(v, sr[(t * TY + rty) * RPT + rr]);
        g_min[0][bt][rowblk * ROWS_BLK + rty * RPT + rr] = fmaxf(v, 0.0f);
    }
}

// ---------------------------------------------------------------------------
// Fold col-min partials across the 64 row-blocks.
// ---------------------------------------------------------------------------
__global__ void __launch_bounds__(256) fold_kernel() {
    const int idx = blockIdx.x * 256 + threadIdx.x;   // 32768 total
    const int bt  = idx >> 12;
    const int col = idx & (N_ - 1);
    float v = 3.0e38f;
#pragma unroll 8
    for (int rb = 0; rb < ROWBLKS; rb++)
        v = fminf(v, g_colpart[bt][rb][col]);
    g_min[1][bt][col] = fmaxf(v, 0.0f);
}

// ---------------------------------------------------------------------------
// Per-(b,t) reduction: chamfer + temperature soft-max hausdorff.
// ---------------------------------------------------------------------------
__device__ __forceinline__ float blockSum(float v, float* s) {
    const int tid = threadIdx.x;
    s[tid] = v; __syncthreads();
    for (int off = 128; off > 0; off >>= 1) {
        if (tid < off) s[tid] += s[tid + off];
        __syncthreads();
    }
    const float r = s[0]; __syncthreads();
    return r;
}
__device__ __forceinline__ float blockMax(float v, float* s) {
    const int tid = threadIdx.x;
    s[tid] = v; __syncthreads();
    for (int off = 128; off > 0; off >>= 1) {
        if (tid < off) s[tid] = fmaxf(s[tid], s[tid + off]);
        __syncthreads();
    }
    const float r = s[0]; __syncthreads();
    return r;
}

__global__ void __launch_bounds__(256) reduce_kernel(
    const void* __restrict__ isctl, const void* __restrict__ pad,
    const void* __restrict__ vis)
{
    __shared__ float sred[256];
    const int bt   = blockIdx.x;
    const int b    = bt >> 2;
    const int mode = g_mask_mode;
    const int tid  = threadIdx.x;
    constexpr int K = N_ / 256;   // 16

    float nv = 0.f, cdp = 0.f, cdt = 0.f;
    float mxp = -3.0e38f, mxt = -3.0e38f;
    float hp[K], ht[K];
    bool  mk[K];

#pragma unroll
    for (int k = 0; k < K; k++) {
        const int n = tid + k * 256;
        const bool msk = !ldmask(isctl, b * N_ + n, mode)
                       &&  ldmask(pad,   b * N_ + n, mode)
                       &&  ldmask(vis,  bt * N_ + n, mode);
        mk[k] = msk;
        const float mp = g_min[0][bt][n];
        const float mt = g_min[1][bt][n];
        if (msk) {
            nv  += 1.0f;
            cdp += (mp > THRESHF) ? 0.0f : mp;
            cdt += (mt > THRESHF) ? 0.0f : mt;
            hp[k] = fminf(mp, THRESHF);
            ht[k] = fminf(mt, THRESHF);
            mxp = fmaxf(mxp, hp[k]);
            mxt = fmaxf(mxt, ht[k]);
        } else { hp[k] = 0.f; ht[k] = 0.f; }
    }

    const float nvT  = blockSum(nv,  sred);
    const float cdpT = blockSum(cdp, sred);
    const float cdtT = blockSum(cdt, sred);
    const float Mp   = blockMax(mxp, sred);
    const float Mt   = blockMax(mxt, sred);
    const bool  anyv = (Mp > -1.0e30f);

    float sep = 0.f, shp = 0.f, set = 0.f, sht = 0.f;
#pragma unroll
    for (int k = 0; k < K; k++) {
        if (mk[k]) {
            const float ep = expf((hp[k] - Mp) * INV_TEMP);
            sep += ep; shp += hp[k] * ep;
            const float et = expf((ht[k] - Mt) * INV_TEMP);
            set += et; sht += ht[k] * et;
        }
    }
    const float sepT = blockSum(sep, sred);
    const float shpT = blockSum(shp, sred);
    const float setT = blockSum(set, sred);
    const float shtT = blockSum(sht, sred);

    if (tid == 0) {
        const float nvc = fmaxf(nvT, 1.0f);
        g_cd[bt] = cdpT / nvc + cdtT / nvc;
        const float rp = anyv ? (shpT / sepT) : 0.0f;
        const float rt = anyv ? (shtT / setT) : 0.0f;
        g_hd[bt] = fmaxf(rp, rt);
    }
}

__global__ void final_kernel(float* __restrict__ out) {
    if (threadIdx.x == 0) {
        float cd = 0.f, hd = 0.f;
        for (int i = 0; i < BT_; i++) { cd += g_cd[i]; hd += g_hd[i]; }
        out[0] = ALPHA_C * (cd / (float)BT_) + (1.0f - ALPHA_C) * (hd / (float)BT_);
    }
}

// ---------------------------------------------------------------------------
extern "C" void kernel_launch(void* const* d_in, const int* in_sizes, int n_in,
                              void* d_out, int out_size) {
    const float* pred = (const float*)d_in[0];
    const float* tgt  = (const float*)d_in[1];
    const void*  isc  = d_in[2];
    const void*  pad  = d_in[3];
    const void*  vis  = d_in[4];

    detect_mask_kernel<<<1, 256>>>((const unsigned char*)pad);
    dist_kernel<<<dim3(ROWBLKS, BT_), 128>>>(pred, tgt, isc, pad, vis);
    fold_kernel<<<(BT_ * N_) / 256, 256>>>();
    reduce_kernel<<<BT_, 256>>>(isc, pad, vis);
    final_kernel<<<1, 32>>>((float*)d_out);
}

// round 3
// speedup vs baseline: 1.4775x; 1.0855x over previous
#include <cuda_runtime.h>

// ============================================================================
// HybridLoss: B=2, T=4, N=4096   —   3 launches: init / dist / epilogue
// u(n,m) = (|p_n|^2 + rowBias_n) + (|t_m|^2 + colBias_m) - 2*dot(p_n,t_m)
// row-min(u) -> min_p (exact for valid rows), col-min(u) -> min_t (valid cols).
// Mins funneled through atomicMax on a descending order-isomorphic uint key.
// Inner loop uses packed fma.rn.f32x2 (2 distances per instruction).
// ============================================================================

#define ALPHA_C  0.5f
#define INV_TEMP 10.0f
#define BIGF     10000000000.0f
#define THRESHF  1000000000.0f

constexpr int N_  = 4096;
constexpr int BT_ = 8;

// dist geometry: block = 64 rows x 2048 cols, 128 threads
constexpr int RPT      = 8;                  // rows per thread (ty*8 .. +7)
constexpr int CPT      = 8;                  // cols per thread per chunk
constexpr int ROWS_BLK = 64;
constexpr int COLS_BLK = 2048;
constexpr int CCH      = 128;                // cols staged per chunk
constexpr int NCHUNKS  = COLS_BLK / CCH;     // 16
constexpr int ROWBLKS  = N_ / ROWS_BLK;      // 64
constexpr int COLBLKS  = N_ / COLS_BLK;      // 2

// Scratch (static device arrays only)
__device__ unsigned g_enc_p[BT_][N_];   // desc-encoded row mins (min_p)
__device__ unsigned g_enc_t[BT_][N_];   // desc-encoded col mins (min_t)
__device__ int      g_mask_mode;        // 0=u8/bool 1=int32 2=float32

// ---------------------------------------------------------------------------
// float <-> descending-ordered uint key.  key is monotone DECREASING in f,
// so atomicMax(key) == fmin(f), and the init value 0 behaves as +inf.
// ---------------------------------------------------------------------------
__device__ __forceinline__ unsigned enc_desc(float f) {
    unsigned b = __float_as_uint(f);
    unsigned asc = (b & 0x80000000u) ? ~b : (b | 0x80000000u);
    return ~asc;
}
__device__ __forceinline__ float dec_desc(unsigned k) {
    unsigned asc = ~k;
    unsigned b = (asc & 0x80000000u) ? (asc ^ 0x80000000u) : ~asc;
    return __uint_as_float(b);
}

// packed f32x2 helpers
__device__ __forceinline__ unsigned long long fma2(
    unsigned long long a, unsigned long long b, unsigned long long c) {
    unsigned long long d;
    asm("fma.rn.f32x2 %0, %1, %2, %3;" : "=l"(d) : "l"(a), "l"(b), "l"(c));
    return d;
}
__device__ __forceinline__ unsigned long long add2(
    unsigned long long a, unsigned long long b) {
    unsigned long long d;
    asm("add.rn.f32x2 %0, %1, %2;" : "=l"(d) : "l"(a), "l"(b));
    return d;
}
__device__ __forceinline__ unsigned long long pack2(float a, float b) {
    unsigned long long r;
    asm("mov.b64 %0, {%1, %2};" : "=l"(r) : "f"(a), "f"(b));
    return r;
}
__device__ __forceinline__ void unpack2(unsigned long long v, float& a, float& b) {
    asm("mov.b64 {%0, %1}, %2;" : "=f"(a), "=f"(b) : "l"(v));
}

__device__ __forceinline__ bool ldmask(const void* p, int i, int mode) {
    if (mode == 0) return ((const unsigned char*)p)[i] != 0;
    if (mode == 1) return ((const int*)p)[i] != 0;
    return ((const float*)p)[i] != 0.0f;
}

// ---------------------------------------------------------------------------
// init: zero encoded-min arrays, zero out[0], detect mask dtype (block 0).
// ---------------------------------------------------------------------------
__global__ void __launch_bounds__(256) init_kernel(
    const unsigned char* __restrict__ pad, float* __restrict__ out)
{
    const int g = blockIdx.x * 256 + threadIdx.x;     // 0..8191
    unsigned* ep = &g_enc_p[0][0];
    unsigned* et = &g_enc_t[0][0];
#pragma unroll
    for (int w = 0; w < 4; w++) { ep[g * 4 + w] = 0u; et[g * 4 + w] = 0u; }

    if (blockIdx.x == 0) {
        __shared__ int c1, c2;
        if (threadIdx.x == 0) { c1 = 0; c2 = 0; out[0] = 0.0f; }
        __syncthreads();
        int l1 = 0, l2 = 0;
        for (int i = threadIdx.x; i < 2048; i += 256) {
            if (pad[4 * i + 1]) l1++;
            if (pad[4 * i + 2]) l2++;
        }
        atomicAdd(&c1, l1);
        atomicAdd(&c2, l2);
        __syncthreads();
        if (threadIdx.x == 0)
            g_mask_mode = (c1 > 64) ? 0 : ((c2 > 64) ? 2 : 1);
    }
}

// ---------------------------------------------------------------------------
// dist: grid (ROWBLKS, COLBLKS, BT_), 128 threads.
// tid = tx*8 + ty  (tx 0..15 -> col group, ty 0..7 -> 8 consecutive rows)
// ---------------------------------------------------------------------------
__global__ void __launch_bounds__(128) dist_kernel(
    const float* __restrict__ pred, const float* __restrict__ tgt,
    const void* __restrict__ isctl, const void* __restrict__ pad,
    const void* __restrict__ vis)
{
    __shared__ float4 sc[CCH * 2];   // per col: (-2x,-2x,-2y,-2y) (-2z,-2z,w,w)

    const int rowblk = blockIdx.x;
    const int colblk = blockIdx.y;
    const int bt     = blockIdx.z;
    const int b      = bt >> 2;
    const int mode   = g_mask_mode;
    const int tid    = threadIdx.x;
    const int tx     = tid >> 3;
    const int ty     = tid & 7;

    // Rows: 4 packed pairs.
    unsigned long long px2[4], py2[4], pz2[4], rw2[4];
    float rmin[RPT];
    const int rbase = rowblk * ROWS_BLK + ty * RPT;
#pragma unroll
    for (int q = 0; q < 4; q++) {
        float x[2], y[2], z[2], w[2];
#pragma unroll
        for (int h = 0; h < 2; h++) {
            const int row = rbase + q * 2 + h;
            const float* rp = pred + ((size_t)bt * N_ + row) * 3;
            x[h] = rp[0]; y[h] = rp[1]; z[h] = rp[2];
            const bool msk = !ldmask(isctl, b * N_ + row, mode)
                           &&  ldmask(pad,   b * N_ + row, mode)
                           &&  ldmask(vis,  bt * N_ + row, mode);
            w[h] = fmaf(x[h], x[h], fmaf(y[h], y[h], z[h] * z[h]))
                 + (msk ? 0.0f : BIGF);
            rmin[q * 2 + h] = 3.0e38f;
        }
        px2[q] = pack2(x[0], x[1]);
        py2[q] = pack2(y[0], y[1]);
        pz2[q] = pack2(z[0], z[1]);
        rw2[q] = pack2(w[0], w[1]);
    }

    for (int chunk = 0; chunk < NCHUNKS; chunk++) {
        __syncthreads();
        {   // stage one column per thread, coordinates pre-duplicated
            const int m = colblk * COLS_BLK + chunk * CCH + tid;
            const float* cp = tgt + ((size_t)bt * N_ + m) * 3;
            const float x = cp[0], y = cp[1], z = cp[2];
            const bool msk = !ldmask(isctl, b * N_ + m, mode)
                           &&  ldmask(pad,   b * N_ + m, mode)
                           &&  ldmask(vis,  bt * N_ + m, mode);
            const float cw = fmaf(x, x, fmaf(y, y, z * z))
                           + (msk ? 0.0f : BIGF);
            sc[2 * tid]     = make_float4(-2.0f * x, -2.0f * x, -2.0f * y, -2.0f * y);
            sc[2 * tid + 1] = make_float4(-2.0f * z, -2.0f * z, cw, cw);
        }
        __syncthreads();

        float cmin[CPT];
#pragma unroll
        for (int j = 0; j < CPT; j++) {
            const int cj = tx * CPT + j;
            const unsigned long long* cd =
                reinterpret_cast<const unsigned long long*>(&sc[2 * cj]);
            const unsigned long long xd = cd[0], yd = cd[1], zd = cd[2], wd = cd[3];
            float cm = 3.0e38f;
#pragma unroll
            for (int q = 0; q < 4; q++) {
                unsigned long long acc = add2(wd, rw2[q]);     // w + rw
                acc = fma2(pz2[q], zd, acc);
                acc = fma2(py2[q], yd, acc);
                acc = fma2(px2[q], xd, acc);
                float lo, hi;
                unpack2(acc, lo, hi);
                rmin[q * 2]     = fminf(rmin[q * 2], lo);
                rmin[q * 2 + 1] = fminf(rmin[q * 2 + 1], hi);
                cm = fminf(cm, fminf(lo, hi));
            }
            cmin[j] = cm;
        }

        // col-min across the 8 ty-lanes of each tx octet
#pragma unroll
        for (int j = 0; j < CPT; j++) {
            cmin[j] = fminf(cmin[j], __shfl_xor_sync(0xffffffffu, cmin[j], 4));
            cmin[j] = fminf(cmin[j], __shfl_xor_sync(0xffffffffu, cmin[j], 2));
            cmin[j] = fminf(cmin[j], __shfl_xor_sync(0xffffffffu, cmin[j], 1));
        }
        if (ty == 0) {
            const int cbase = colblk * COLS_BLK + chunk * CCH + tx * CPT;
#pragma unroll
            for (int j = 0; j < CPT; j++)
                atomicMax(&g_enc_t[bt][cbase + j], enc_desc(cmin[j]));
        }
    }

    // row-min: fold the 4 tx groups within each warp, then atomicMax.
#pragma unroll
    for (int r = 0; r < RPT; r++) {
        rmin[r] = fminf(rmin[r], __shfl_xor_sync(0xffffffffu, rmin[r], 8));
        rmin[r] = fminf(rmin[r], __shfl_xor_sync(0xffffffffu, rmin[r], 16));
    }
    if ((tid & 31) < 8) {   // one lane per ty per warp
#pragma unroll
        for (int r = 0; r < RPT; r++)
            atomicMax(&g_enc_p[bt][rbase + r], enc_desc(rmin[r]));
    }
}

// ---------------------------------------------------------------------------
// epilogue: grid=8 (bt), 1024 threads. chamfer + soft-hausdorff, atomicAdd out.
// ---------------------------------------------------------------------------
__device__ __forceinline__ float blockRed(float v, float* s, bool ismax) {
    const int w = threadIdx.x >> 5, l = threadIdx.x & 31;
#pragma unroll
    for (int o = 16; o > 0; o >>= 1) {
        const float x = __shfl_xor_sync(0xffffffffu, v, o);
        v = ismax ? fmaxf(v, x) : (v + x);
    }
    __syncthreads();
    if (l == 0) s[w] = v;
    __syncthreads();
    if (w == 0) {
        v = s[l];
#pragma unroll
        for (int o = 16; o > 0; o >>= 1) {
            const float x = __shfl_xor_sync(0xffffffffu, v, o);
            v = ismax ? fmaxf(v, x) : (v + x);
        }
        if (l == 0) s[0] = v;
    }
    __syncthreads();
    return s[0];
}

__global__ void __launch_bounds__(1024) epilogue_kernel(
    const void* __restrict__ isctl, const void* __restrict__ pad,
    const void* __restrict__ vis, float* __restrict__ out)
{
    __shared__ float s[32];
    const int bt   = blockIdx.x;
    const int b    = bt >> 2;
    const int mode = g_mask_mode;
    const int tid  = threadIdx.x;
    constexpr int K = N_ / 1024;   // 4

    float nv = 0.f, cdp = 0.f, cdt = 0.f;
    float mxp = -3.0e38f, mxt = -3.0e38f;
    float hp[K], ht[K];
    bool  mk[K];

#pragma unroll
    for (int k = 0; k < K; k++) {
        const int n = tid + k * 1024;
        const bool msk = !ldmask(isctl, b * N_ + n, mode)
                       &&  ldmask(pad,   b * N_ + n, mode)
                       &&  ldmask(vis,  bt * N_ + n, mode);
        mk[k] = msk;
        const float mp = fmaxf(dec_desc(g_enc_p[bt][n]), 0.0f);
        const float mt = fmaxf(dec_desc(g_enc_t[bt][n]), 0.0f);
        if (msk) {
            nv  += 1.0f;
            cdp += (mp > THRESHF) ? 0.0f : mp;
            cdt += (mt > THRESHF) ? 0.0f : mt;
            hp[k] = fminf(mp, THRESHF);
            ht[k] = fminf(mt, THRESHF);
            mxp = fmaxf(mxp, hp[k]);
            mxt = fmaxf(mxt, ht[k]);
        } else { hp[k] = 0.f; ht[k] = 0.f; }
    }

    const float nvT  = blockRed(nv,  s, false);
    const float cdpT = blockRed(cdp, s, false);
    const float cdtT = blockRed(cdt, s, false);
    const float Mp   = blockRed(mxp, s, true);
    const float Mt   = blockRed(mxt, s, true);
    const bool  anyv = (Mp > -1.0e30f);

    float sep = 0.f, shp = 0.f, set = 0.f, sht = 0.f;
#pragma unroll
    for (int k = 0; k < K; k++) {
        if (mk[k]) {
            const float ep = expf((hp[k] - Mp) * INV_TEMP);
            sep += ep; shp += hp[k] * ep;
            const float et = expf((ht[k] - Mt) * INV_TEMP);
            set += et; sht += ht[k] * et;
        }
    }
    const float sepT = blockRed(sep, s, false);
    const float shpT = blockRed(shp, s, false);
    const float setT = blockRed(set, s, false);
    const float shtT = blockRed(sht, s, false);

    if (tid == 0) {
        const float nvc = fmaxf(nvT, 1.0f);
        const float cd  = cdpT / nvc + cdtT / nvc;
        const float rp  = anyv ? (shpT / sepT) : 0.0f;
        const float rt  = anyv ? (shtT / setT) : 0.0f;
        const float hd  = fmaxf(rp, rt);
        atomicAdd(out, (ALPHA_C * cd + (1.0f - ALPHA_C) * hd) * (1.0f / BT_));
    }
}

// ---------------------------------------------------------------------------
extern "C" void kernel_launch(void* const* d_in, const int* in_sizes, int n_in,
                              void* d_out, int out_size) {
    const float* pred = (const float*)d_in[0];
    const float* tgt  = (const float*)d_in[1];
    const void*  isc  = d_in[2];
    const void*  pad  = d_in[3];
    const void*  vis  = d_in[4];
    float*       out  = (float*)d_out;

    init_kernel<<<32, 256>>>((const unsigned char*)pad, out);
    dist_kernel<<<dim3(ROWBLKS, COLBLKS, BT_), 128>>>(pred, tgt, isc, pad, vis);
    epilogue_kernel<<<BT_, 1024>>>(isc, pad, vis, out);
}